// round 4
// baseline (speedup 1.0000x reference)
#include <cuda_runtime.h>
#include <cuda_bf16.h>
#include <cstdint>

#define B_SZ 32
#define T_SZ 2048
#define DIN  1024
#define HID  2048
#define BM   128
#define BN   128
#define BK   32          // fp32 elements per K-chunk (128B rows -> SW128)
#define NCHUNK (DIN / BK)

// ---------------- device-global scratch (allocation-free) ----------------
__device__ float g_part[(size_t)16 * B_SZ * HID];   // [tt][b][n] partial column sums
__device__ float g_pooled[B_SZ * HID];

// ---------------- helpers ----------------
__device__ __forceinline__ uint32_t smem_u32(const void* p) {
    uint32_t a;
    asm("{ .reg .u64 t; cvta.to.shared.u64 t, %1; cvt.u32.u64 %0, t; }" : "=r"(a) : "l"(p));
    return a;
}
__device__ __forceinline__ void ldsm_x4(uint32_t& r0, uint32_t& r1, uint32_t& r2, uint32_t& r3,
                                        uint32_t addr) {
    asm volatile("ldmatrix.sync.aligned.m8n8.x4.shared.b16 {%0,%1,%2,%3}, [%4];"
                 : "=r"(r0), "=r"(r1), "=r"(r2), "=r"(r3) : "r"(addr));
}
__device__ __forceinline__ uint32_t f2tf32(uint32_t bits) {
    uint32_t d;
    asm("cvt.rna.tf32.f32 %0, %1;" : "=r"(d) : "f"(__uint_as_float(bits)));
    return d;
}
__device__ __forceinline__ void mma_tf32(float* c, const uint32_t* a, const uint32_t* b) {
    asm volatile(
        "mma.sync.aligned.m16n8k8.row.col.f32.tf32.tf32.f32 "
        "{%0,%1,%2,%3}, {%4,%5,%6,%7}, {%8,%9}, {%0,%1,%2,%3};"
        : "+f"(c[0]), "+f"(c[1]), "+f"(c[2]), "+f"(c[3])
        : "r"(a[0]), "r"(a[1]), "r"(a[2]), "r"(a[3]), "r"(b[0]), "r"(b[1]));
}
#define CP_ASYNC16(dst, src) \
    asm volatile("cp.async.cg.shared.global [%0], [%1], 16;" :: "r"(dst), "l"(src))
#define CP_COMMIT() asm volatile("cp.async.commit_group;" ::: "memory")
#define CP_WAIT2()  asm volatile("cp.async.wait_group 2;" ::: "memory")

// ---------------- chunk loader: 128 rows x 32 fp32 (128B/row), SW128 swizzle ----------------
__device__ __forceinline__ void load_chunk(uint32_t smA, uint32_t smB,
                                           const float* gA, const float* gB,
                                           int k0, int tid) {
#pragma unroll
    for (int j = 0; j < 4; j++) {
        int idx = tid + j * 256;
        int row = idx >> 3, seg = idx & 7;
        uint32_t sw = (uint32_t)(row * 128) + (((uint32_t)seg * 16) ^ (((uint32_t)row & 7) << 4));
        CP_ASYNC16(smA + sw, gA + (size_t)row * DIN + k0 + seg * 4);
    }
#pragma unroll
    for (int j = 0; j < 4; j++) {
        int idx = tid + j * 256;
        int row = idx >> 3, seg = idx & 7;
        uint32_t sw = (uint32_t)(row * 128) + (((uint32_t)seg * 16) ^ (((uint32_t)row & 7) << 4));
        CP_ASYNC16(smB + sw, gB + (size_t)row * DIN + k0 + seg * 4);
    }
}

// ---------------- SMEM layout ----------------
#define SM_B1   0        // 128 floats (512B)
#define SM_PART 512      // 4 x 128 floats (2KB)
#define SM_BUFA 4096     // 3 stages x 16KB
#define SM_BUFB 53248    // 3 stages x 16KB
#define SMEM_TOTAL 102400

// ---------------- fused GEMM tile (relu(h@W1^T+b1)) + column partial sums ----------------
// grid: (16 nt, 16 tt, 32 b); 256 threads; warps 4(M)x2(N), warp tile 32x64
__global__ void __launch_bounds__(256, 2) gemm_kernel(const float* __restrict__ h,
                                                      const float* __restrict__ W1,
                                                      const int* __restrict__ tl,
                                                      const float* __restrict__ b1) {
    const int nt = blockIdx.x, tt = blockIdx.y, b = blockIdx.z;
    const int len = tl[b];
    if (tt * BM >= len) return;

    extern __shared__ char smem[];
    float* sb1  = (float*)(smem + SM_B1);
    float* part = (float*)(smem + SM_PART);
    const uint32_t sbase = smem_u32(smem);
    const uint32_t smA = sbase + SM_BUFA;
    const uint32_t smB = sbase + SM_BUFB;

    const int tid = threadIdx.x, lane = tid & 31, wid = tid >> 5;
    const int wm = wid >> 1, wn = wid & 1;

    if (tid < 128) sb1[tid] = b1[nt * BN + tid];

    const float* gA = h  + ((size_t)b * T_SZ + (size_t)tt * BM) * DIN;
    const float* gB = W1 + (size_t)nt * BN * DIN;

    float acc[2][8][4];
#pragma unroll
    for (int i = 0; i < 2; i++)
#pragma unroll
        for (int j = 0; j < 8; j++)
#pragma unroll
            for (int k = 0; k < 4; k++) acc[i][j][k] = 0.f;

    // ldmatrix-as-tf32 addressing: each 8x8 b16 matrix = 8 rows x 4 fp32
    const int r8   = lane & 7;
    const uint32_t xorv = (uint32_t)r8 << 4;
    const uint32_t aColSel = ((lane >> 4) & 1) * 16;   // A: mats 2,3 -> cols +4 fp32
    const uint32_t bColSel = ((lane >> 3) & 1) * 16;   // B: mats 1,3 -> k +4
    uint32_t aRowOff[2], bRowOff[4];
#pragma unroll
    for (int mt = 0; mt < 2; mt++)
        aRowOff[mt] = (uint32_t)((wm * 32 + mt * 16 + ((lane >> 3) & 1) * 8 + r8) * 128);
#pragma unroll
    for (int p = 0; p < 4; p++)
        bRowOff[p] = (uint32_t)((wn * 64 + p * 16 + ((lane >> 4) & 1) * 8 + r8) * 128);

    // 3-stage cp.async pipeline
    load_chunk(smA, smB, gA, gB, 0, tid);
    CP_COMMIT();
    load_chunk(smA + 16384, smB + 16384, gA, gB, BK, tid);
    CP_COMMIT();

    for (int c = 0; c < NCHUNK; c++) {
        if (c + 2 < NCHUNK)
            load_chunk(smA + ((c + 2) % 3) * 16384, smB + ((c + 2) % 3) * 16384,
                       gA, gB, (c + 2) * BK, tid);
        CP_COMMIT();          // always commit (possibly empty group) to keep counts uniform
        CP_WAIT2();
        __syncthreads();

        const uint32_t bufA = smA + (c % 3) * 16384;
        const uint32_t bufB = smB + (c % 3) * 16384;
#pragma unroll
        for (int ks = 0; ks < 4; ks++) {
            const uint32_t kb = (uint32_t)ks * 32;
            uint32_t a[2][4];
#pragma unroll
            for (int mt = 0; mt < 2; mt++) {
                ldsm_x4(a[mt][0], a[mt][1], a[mt][2], a[mt][3],
                        bufA + aRowOff[mt] + ((kb + aColSel) ^ xorv));
                a[mt][0] = f2tf32(a[mt][0]); a[mt][1] = f2tf32(a[mt][1]);
                a[mt][2] = f2tf32(a[mt][2]); a[mt][3] = f2tf32(a[mt][3]);
            }
#pragma unroll
            for (int p = 0; p < 4; p++) {
                uint32_t q0, q1, q2, q3;
                ldsm_x4(q0, q1, q2, q3, bufB + bRowOff[p] + ((kb + bColSel) ^ xorv));
                uint32_t bfa[2] = { f2tf32(q0), f2tf32(q1) };
                uint32_t bfb[2] = { f2tf32(q2), f2tf32(q3) };
#pragma unroll
                for (int mt = 0; mt < 2; mt++) {
                    mma_tf32(acc[mt][2 * p],     a[mt], bfa);
                    mma_tf32(acc[mt][2 * p + 1], a[mt], bfb);
                }
            }
        }
        __syncthreads();
    }

    // ---- epilogue: bias + relu + row mask + deterministic column reduce ----
    const int r0g = tt * BM + wm * 32 + (lane >> 2);
#pragma unroll
    for (int n8 = 0; n8 < 8; n8++) {
        const int c0 = wn * 64 + n8 * 8 + (lane & 3) * 2;
        const float bias0 = sb1[c0], bias1 = sb1[c0 + 1];
        float s0 = 0.f, s1 = 0.f;
#pragma unroll
        for (int mt = 0; mt < 2; mt++) {
            const int rr = r0g + mt * 16;
            if (rr < len) {
                s0 += fmaxf(acc[mt][n8][0] + bias0, 0.f);
                s1 += fmaxf(acc[mt][n8][1] + bias1, 0.f);
            }
            if (rr + 8 < len) {
                s0 += fmaxf(acc[mt][n8][2] + bias0, 0.f);
                s1 += fmaxf(acc[mt][n8][3] + bias1, 0.f);
            }
        }
#pragma unroll
        for (int o = 4; o < 32; o <<= 1) {
            s0 += __shfl_xor_sync(0xffffffffu, s0, o);
            s1 += __shfl_xor_sync(0xffffffffu, s1, o);
        }
        if (lane < 4) {
            part[wm * 128 + c0] = s0;
            part[wm * 128 + c0 + 1] = s1;
        }
    }
    __syncthreads();
    if (tid < 128) {
        float v = part[tid] + part[128 + tid] + part[256 + tid] + part[384 + tid];
        g_part[((size_t)tt * B_SZ + b) * HID + nt * BN + tid] = v;
    }
}

// ---------------- reduce partials over t-tiles, divide by len ----------------
__global__ void __launch_bounds__(256) pool_reduce_kernel(const int* __restrict__ tl) {
    int idx = blockIdx.x * 256 + threadIdx.x;   // 65536 = B*HID
    int b = idx >> 11;
    int len = tl[b];
    int ntt = (len + BM - 1) >> 7;
    float s = 0.f;
    for (int t = 0; t < ntt; t++) s += g_part[((size_t)t * B_SZ + b) * HID + (idx & (HID - 1))];
    g_pooled[idx] = s / (float)len;
}

// ---------------- final score ----------------
__global__ void __launch_bounds__(64) score_kernel(const float* __restrict__ W2,
                                                   const float* __restrict__ b2,
                                                   float* __restrict__ out) {
    __shared__ float sm[2][2];
    int b = blockIdx.x, tid = threadIdx.x, wid = tid >> 5, lane = tid & 31;
    float s0 = 0.f, s1 = 0.f;
    const float* p = g_pooled + b * HID;
    for (int h = tid; h < HID; h += 64) {
        float v = p[h];
        s0 += v * W2[h];
        s1 += v * W2[HID + h];
    }
#pragma unroll
    for (int o = 16; o > 0; o >>= 1) {
        s0 += __shfl_xor_sync(0xffffffffu, s0, o);
        s1 += __shfl_xor_sync(0xffffffffu, s1, o);
    }
    if (lane == 0) { sm[wid][0] = s0; sm[wid][1] = s1; }
    __syncthreads();
    if (tid == 0) {
        out[b * 2 + 0] = sm[0][0] + sm[1][0] + b2[0];
        out[b * 2 + 1] = sm[0][1] + sm[1][1] + b2[1];
    }
}

// ---------------- launch ----------------
extern "C" void kernel_launch(void* const* d_in, const int* in_sizes, int n_in,
                              void* d_out, int out_size) {
    const float* h  = (const float*)d_in[0];
    const int*   tl = (const int*)d_in[1];
    const float* W1 = (const float*)d_in[2];
    const float* b1 = (const float*)d_in[3];
    const float* W2 = (const float*)d_in[4];
    const float* b2 = (const float*)d_in[5];
    float* out = (float*)d_out;

    static bool attr_set = false;
    if (!attr_set) {
        cudaFuncSetAttribute(gemm_kernel,
                             cudaFuncAttributeMaxDynamicSharedMemorySize, SMEM_TOTAL);
        attr_set = true;
    }

    gemm_kernel<<<dim3(HID / BN, T_SZ / BM, B_SZ), 256, SMEM_TOTAL>>>(h, W1, tl, b1);
    pool_reduce_kernel<<<(B_SZ * HID) / 256, 256>>>(tl);
    score_kernel<<<B_SZ, 64>>>(W2, b2, out);
}

// round 5
// speedup vs baseline: 1.0376x; 1.0376x over previous
#include <cuda_runtime.h>
#include <cuda_bf16.h>
#include <cstdint>

#define B_SZ 32
#define T_SZ 2048
#define DIN  1024
#define HID  2048
#define BM   128
#define BN   128
#define BK   32          // fp32 elements per K-chunk (128B rows -> SW128)
#define NCHUNK (DIN / BK)

// ---------------- device-global scratch (allocation-free) ----------------
__device__ __align__(16) float g_h32 [(size_t)B_SZ * T_SZ * DIN];  // 256 MB (tf32-rounded h)
__device__ __align__(16) float g_w132[(size_t)HID * DIN];          // 8 MB  (tf32-rounded W1)
__device__ float g_part[(size_t)16 * B_SZ * HID];                  // 4 MB [tt][b][n]
__device__ float g_pooled[B_SZ * HID];

// ---------------- helpers ----------------
__device__ __forceinline__ uint32_t smem_u32(const void* p) {
    uint32_t a;
    asm("{ .reg .u64 t; cvta.to.shared.u64 t, %1; cvt.u32.u64 %0, t; }" : "=r"(a) : "l"(p));
    return a;
}
__device__ __forceinline__ void ldsm_x4(uint32_t& r0, uint32_t& r1, uint32_t& r2, uint32_t& r3,
                                        uint32_t addr) {
    asm volatile("ldmatrix.sync.aligned.m8n8.x4.shared.b16 {%0,%1,%2,%3}, [%4];"
                 : "=r"(r0), "=r"(r1), "=r"(r2), "=r"(r3) : "r"(addr));
}
__device__ __forceinline__ float f2tf32f(float x) {
    uint32_t d;
    asm("cvt.rna.tf32.f32 %0, %1;" : "=r"(d) : "f"(x));
    return __uint_as_float(d);
}
__device__ __forceinline__ void mma_tf32(float* c, const uint32_t* a, const uint32_t* b) {
    asm volatile(
        "mma.sync.aligned.m16n8k8.row.col.f32.tf32.tf32.f32 "
        "{%0,%1,%2,%3}, {%4,%5,%6,%7}, {%8,%9}, {%0,%1,%2,%3};"
        : "+f"(c[0]), "+f"(c[1]), "+f"(c[2]), "+f"(c[3])
        : "r"(a[0]), "r"(a[1]), "r"(a[2]), "r"(a[3]), "r"(b[0]), "r"(b[1]));
}
#define CP_ASYNC16(dst, src) \
    asm volatile("cp.async.cg.shared.global [%0], [%1], 16;" :: "r"(dst), "l"(src))
#define CP_COMMIT() asm volatile("cp.async.commit_group;" ::: "memory")
#define CP_WAIT2()  asm volatile("cp.async.wait_group 2;" ::: "memory")

// ---------------- prepass: round to tf32-representable fp32 ----------------
__global__ void __launch_bounds__(256) rnd_h_kernel(const float4* __restrict__ src,
                                                    const int* __restrict__ tl) {
    unsigned g = blockIdx.x * 256u + threadIdx.x;       // one group = 4 floats
    unsigned b = g >> 19;                               // 524288 float4 per batch
    unsigned t = (g >> 8) & (T_SZ - 1);                 // 256 float4 per t-row
    int len = tl[b];
    unsigned tmax = ((unsigned)len + 127u) & ~127u;     // only rows the GEMM reads
    if (t >= tmax) return;
    float4 v = src[g];
    v.x = f2tf32f(v.x); v.y = f2tf32f(v.y); v.z = f2tf32f(v.z); v.w = f2tf32f(v.w);
    reinterpret_cast<float4*>(g_h32)[g] = v;
}

__global__ void __launch_bounds__(256) rnd_w1_kernel(const float4* __restrict__ src) {
    unsigned g = blockIdx.x * 256u + threadIdx.x;
    float4 v = src[g];
    v.x = f2tf32f(v.x); v.y = f2tf32f(v.y); v.z = f2tf32f(v.z); v.w = f2tf32f(v.w);
    reinterpret_cast<float4*>(g_w132)[g] = v;
}

// ---------------- chunk loader: 128 rows x 32 fp32 (128B/row), SW128 swizzle ----------------
__device__ __forceinline__ void load_chunk(uint32_t smA, uint32_t smB,
                                           const float* gA, const float* gB,
                                           int k0, int tid) {
#pragma unroll
    for (int j = 0; j < 4; j++) {
        int idx = tid + j * 256;
        int row = idx >> 3, seg = idx & 7;
        uint32_t sw = (uint32_t)(row * 128) + (((uint32_t)seg * 16) ^ (((uint32_t)row & 7) << 4));
        CP_ASYNC16(smA + sw, gA + (size_t)row * DIN + k0 + seg * 4);
    }
#pragma unroll
    for (int j = 0; j < 4; j++) {
        int idx = tid + j * 256;
        int row = idx >> 3, seg = idx & 7;
        uint32_t sw = (uint32_t)(row * 128) + (((uint32_t)seg * 16) ^ (((uint32_t)row & 7) << 4));
        CP_ASYNC16(smB + sw, gB + (size_t)row * DIN + k0 + seg * 4);
    }
}

// ---------------- SMEM layout ----------------
#define SM_B1   0        // 128 floats (512B)
#define SM_PART 512      // 4 x 128 floats (2KB)
#define SM_BUFA 4096     // 3 stages x 16KB
#define SM_BUFB 53248    // 3 stages x 16KB
#define SMEM_TOTAL 102400

// ---------------- fused GEMM tile (relu(h@W1^T+b1)) + column partial sums ----------------
// grid: (16 nt, 16 tt, 32 b); 256 threads; warps 4(M)x2(N), warp tile 32x64
__global__ void __launch_bounds__(256, 2) gemm_kernel(const int* __restrict__ tl,
                                                      const float* __restrict__ b1) {
    const int nt = blockIdx.x, tt = blockIdx.y, b = blockIdx.z;
    const int len = tl[b];
    if (tt * BM >= len) return;

    extern __shared__ char smem[];
    float* sb1  = (float*)(smem + SM_B1);
    float* part = (float*)(smem + SM_PART);
    const uint32_t sbase = smem_u32(smem);
    const uint32_t smA = sbase + SM_BUFA;
    const uint32_t smB = sbase + SM_BUFB;

    const int tid = threadIdx.x, lane = tid & 31, wid = tid >> 5;
    const int wm = wid >> 1, wn = wid & 1;

    if (tid < 128) sb1[tid] = b1[nt * BN + tid];

    const float* gA = g_h32  + ((size_t)b * T_SZ + (size_t)tt * BM) * DIN;
    const float* gB = g_w132 + (size_t)nt * BN * DIN;

    float acc[2][8][4];
#pragma unroll
    for (int i = 0; i < 2; i++)
#pragma unroll
        for (int j = 0; j < 8; j++)
#pragma unroll
            for (int k = 0; k < 4; k++) acc[i][j][k] = 0.f;

    // ldmatrix-as-tf32 addressing: each 8x8 b16 matrix = 8 rows x 4 fp32
    const int r8   = lane & 7;
    const uint32_t xorv = (uint32_t)r8 << 4;
    const uint32_t aColSel = ((lane >> 4) & 1) * 16;   // A: mats 2,3 -> cols +4 fp32
    const uint32_t bColSel = ((lane >> 3) & 1) * 16;   // B: mats 1,3 -> k +4
    uint32_t aRowOff[2], bRowOff[4];
#pragma unroll
    for (int mt = 0; mt < 2; mt++)
        aRowOff[mt] = (uint32_t)((wm * 32 + mt * 16 + ((lane >> 3) & 1) * 8 + r8) * 128);
#pragma unroll
    for (int p = 0; p < 4; p++)
        bRowOff[p] = (uint32_t)((wn * 64 + p * 16 + ((lane >> 4) & 1) * 8 + r8) * 128);

    // 3-stage cp.async pipeline
    load_chunk(smA, smB, gA, gB, 0, tid);
    CP_COMMIT();
    load_chunk(smA + 16384, smB + 16384, gA, gB, BK, tid);
    CP_COMMIT();

    for (int c = 0; c < NCHUNK; c++) {
        if (c + 2 < NCHUNK)
            load_chunk(smA + ((c + 2) % 3) * 16384, smB + ((c + 2) % 3) * 16384,
                       gA, gB, (c + 2) * BK, tid);
        CP_COMMIT();          // uniform group count (possibly empty)
        CP_WAIT2();
        __syncthreads();

        const uint32_t bufA = smA + (c % 3) * 16384;
        const uint32_t bufB = smB + (c % 3) * 16384;
#pragma unroll
        for (int ks = 0; ks < 4; ks++) {
            const uint32_t kb = (uint32_t)ks * 32;
            uint32_t a[2][4];
#pragma unroll
            for (int mt = 0; mt < 2; mt++)
                ldsm_x4(a[mt][0], a[mt][1], a[mt][2], a[mt][3],
                        bufA + aRowOff[mt] + ((kb + aColSel) ^ xorv));
#pragma unroll
            for (int p = 0; p < 4; p++) {
                uint32_t q0, q1, q2, q3;
                ldsm_x4(q0, q1, q2, q3, bufB + bRowOff[p] + ((kb + bColSel) ^ xorv));
                uint32_t bfa[2] = { q0, q1 };
                uint32_t bfb[2] = { q2, q3 };
#pragma unroll
                for (int mt = 0; mt < 2; mt++) {
                    mma_tf32(acc[mt][2 * p],     a[mt], bfa);
                    mma_tf32(acc[mt][2 * p + 1], a[mt], bfb);
                }
            }
        }
        __syncthreads();
    }

    // ---- epilogue: bias + relu + row mask + deterministic column reduce ----
    const int r0g = tt * BM + wm * 32 + (lane >> 2);
#pragma unroll
    for (int n8 = 0; n8 < 8; n8++) {
        const int c0 = wn * 64 + n8 * 8 + (lane & 3) * 2;
        const float bias0 = sb1[c0], bias1 = sb1[c0 + 1];
        float s0 = 0.f, s1 = 0.f;
#pragma unroll
        for (int mt = 0; mt < 2; mt++) {
            const int rr = r0g + mt * 16;
            if (rr < len) {
                s0 += fmaxf(acc[mt][n8][0] + bias0, 0.f);
                s1 += fmaxf(acc[mt][n8][1] + bias1, 0.f);
            }
            if (rr + 8 < len) {
                s0 += fmaxf(acc[mt][n8][2] + bias0, 0.f);
                s1 += fmaxf(acc[mt][n8][3] + bias1, 0.f);
            }
        }
#pragma unroll
        for (int o = 4; o < 32; o <<= 1) {
            s0 += __shfl_xor_sync(0xffffffffu, s0, o);
            s1 += __shfl_xor_sync(0xffffffffu, s1, o);
        }
        if (lane < 4) {
            part[wm * 128 + c0] = s0;
            part[wm * 128 + c0 + 1] = s1;
        }
    }
    __syncthreads();
    if (tid < 128) {
        float v = part[tid] + part[128 + tid] + part[256 + tid] + part[384 + tid];
        g_part[((size_t)tt * B_SZ + b) * HID + nt * BN + tid] = v;
    }
}

// ---------------- reduce partials over t-tiles, divide by len ----------------
__global__ void __launch_bounds__(256) pool_reduce_kernel(const int* __restrict__ tl) {
    int idx = blockIdx.x * 256 + threadIdx.x;   // 65536 = B*HID
    int b = idx >> 11;
    int len = tl[b];
    int ntt = (len + BM - 1) >> 7;
    float s = 0.f;
    for (int t = 0; t < ntt; t++) s += g_part[((size_t)t * B_SZ + b) * HID + (idx & (HID - 1))];
    g_pooled[idx] = s / (float)len;
}

// ---------------- final score ----------------
__global__ void __launch_bounds__(64) score_kernel(const float* __restrict__ W2,
                                                   const float* __restrict__ b2,
                                                   float* __restrict__ out) {
    __shared__ float sm[2][2];
    int b = blockIdx.x, tid = threadIdx.x, wid = tid >> 5, lane = tid & 31;
    float s0 = 0.f, s1 = 0.f;
    const float* p = g_pooled + b * HID;
    for (int h = tid; h < HID; h += 64) {
        float v = p[h];
        s0 += v * W2[h];
        s1 += v * W2[HID + h];
    }
#pragma unroll
    for (int o = 16; o > 0; o >>= 1) {
        s0 += __shfl_xor_sync(0xffffffffu, s0, o);
        s1 += __shfl_xor_sync(0xffffffffu, s1, o);
    }
    if (lane == 0) { sm[wid][0] = s0; sm[wid][1] = s1; }
    __syncthreads();
    if (tid == 0) {
        out[b * 2 + 0] = sm[0][0] + sm[1][0] + b2[0];
        out[b * 2 + 1] = sm[0][1] + sm[1][1] + b2[1];
    }
}

// ---------------- launch ----------------
extern "C" void kernel_launch(void* const* d_in, const int* in_sizes, int n_in,
                              void* d_out, int out_size) {
    const float* h  = (const float*)d_in[0];
    const int*   tl = (const int*)d_in[1];
    const float* W1 = (const float*)d_in[2];
    const float* b1 = (const float*)d_in[3];
    const float* W2 = (const float*)d_in[4];
    const float* b2 = (const float*)d_in[5];
    float* out = (float*)d_out;

    static bool attr_set = false;
    if (!attr_set) {
        cudaFuncSetAttribute(gemm_kernel,
                             cudaFuncAttributeMaxDynamicSharedMemorySize, SMEM_TOTAL);
        attr_set = true;
    }

    rnd_h_kernel<<<(B_SZ * T_SZ * DIN / 4) / 256, 256>>>((const float4*)h, tl);
    rnd_w1_kernel<<<(HID * DIN / 4) / 256, 256>>>((const float4*)W1);
    gemm_kernel<<<dim3(HID / BN, T_SZ / BM, B_SZ), 256, SMEM_TOTAL>>>(tl, b1);
    pool_reduce_kernel<<<(B_SZ * HID) / 256, 256>>>(tl);
    score_kernel<<<B_SZ, 64>>>(W2, b2, out);
}

// round 6
// speedup vs baseline: 1.1364x; 1.0953x over previous
#include <cuda_runtime.h>
#include <cuda_bf16.h>
#include <cstdint>

#define B_SZ 32
#define T_SZ 2048
#define DIN  1024
#define HID  2048
#define BM   128
#define BN   128
#define BK   32          // fp32 elements per K-chunk (128B rows -> SW128)
#define NCHUNK (DIN / BK)

// ---------------- device-global scratch (allocation-free) ----------------
__device__ __align__(16) float g_w132[(size_t)HID * DIN];          // 8 MB (tf32-rounded W1)
__device__ float g_part[(size_t)16 * B_SZ * HID];                  // 4 MB [tt][b][n]
__device__ float g_pooled[B_SZ * HID];

// ---------------- helpers ----------------
__device__ __forceinline__ uint32_t smem_u32(const void* p) {
    uint32_t a;
    asm("{ .reg .u64 t; cvta.to.shared.u64 t, %1; cvt.u32.u64 %0, t; }" : "=r"(a) : "l"(p));
    return a;
}
__device__ __forceinline__ void ldsm_x4(uint32_t& r0, uint32_t& r1, uint32_t& r2, uint32_t& r3,
                                        uint32_t addr) {
    asm volatile("ldmatrix.sync.aligned.m8n8.x4.shared.b16 {%0,%1,%2,%3}, [%4];"
                 : "=r"(r0), "=r"(r1), "=r"(r2), "=r"(r3) : "r"(addr));
}
__device__ __forceinline__ float f2tf32f(float x) {
    uint32_t d;
    asm("cvt.rna.tf32.f32 %0, %1;" : "=r"(d) : "f"(x));
    return __uint_as_float(d);
}
__device__ __forceinline__ uint32_t f2tf32u(uint32_t bits) {
    uint32_t d;
    asm("cvt.rna.tf32.f32 %0, %1;" : "=r"(d) : "f"(__uint_as_float(bits)));
    return d;
}
__device__ __forceinline__ void mma_tf32(float* c, const uint32_t* a, const uint32_t* b) {
    asm volatile(
        "mma.sync.aligned.m16n8k8.row.col.f32.tf32.tf32.f32 "
        "{%0,%1,%2,%3}, {%4,%5,%6,%7}, {%8,%9}, {%0,%1,%2,%3};"
        : "+f"(c[0]), "+f"(c[1]), "+f"(c[2]), "+f"(c[3])
        : "r"(a[0]), "r"(a[1]), "r"(a[2]), "r"(a[3]), "r"(b[0]), "r"(b[1]));
}
#define CP_ASYNC16(dst, src) \
    asm volatile("cp.async.cg.shared.global [%0], [%1], 16;" :: "r"(dst), "l"(src))
#define CP_COMMIT() asm volatile("cp.async.commit_group;" ::: "memory")
#define CP_WAIT2()  asm volatile("cp.async.wait_group 2;" ::: "memory")

// ---------------- prepass: round W1 to tf32-representable fp32 (8MB, ~3us) ----------------
__global__ void __launch_bounds__(256) rnd_w1_kernel(const float4* __restrict__ src) {
    unsigned g = blockIdx.x * 256u + threadIdx.x;
    float4 v = src[g];
    v.x = f2tf32f(v.x); v.y = f2tf32f(v.y); v.z = f2tf32f(v.z); v.w = f2tf32f(v.w);
    reinterpret_cast<float4*>(g_w132)[g] = v;
}

// ---------------- chunk loader: 128 rows x 32 fp32 (128B/row), SW128 swizzle ----------------
__device__ __forceinline__ void load_chunk(uint32_t smA, uint32_t smB,
                                           const float* gA, const float* gB,
                                           int k0, int tid) {
#pragma unroll
    for (int j = 0; j < 4; j++) {
        int idx = tid + j * 256;
        int row = idx >> 3, seg = idx & 7;
        uint32_t sw = (uint32_t)(row * 128) + (((uint32_t)seg * 16) ^ (((uint32_t)row & 7) << 4));
        CP_ASYNC16(smA + sw, gA + (size_t)row * DIN + k0 + seg * 4);
    }
#pragma unroll
    for (int j = 0; j < 4; j++) {
        int idx = tid + j * 256;
        int row = idx >> 3, seg = idx & 7;
        uint32_t sw = (uint32_t)(row * 128) + (((uint32_t)seg * 16) ^ (((uint32_t)row & 7) << 4));
        CP_ASYNC16(smB + sw, gB + (size_t)row * DIN + k0 + seg * 4);
    }
}

// ---------------- SMEM layout ----------------
#define SM_B1   0        // 128 floats (512B)
#define SM_PART 512      // 4 x 128 floats (2KB)
#define SM_BUFA 4096     // 3 stages x 16KB
#define SM_BUFB 53248    // 3 stages x 16KB
#define SMEM_TOTAL 102400

// ---------------- fused GEMM tile (relu(h@W1^T+b1)) + column partial sums ----------------
// grid: (16 nt, 16 tt, 32 b); 256 threads; warps 4(M)x2(N), warp tile 32x64
// A = raw fp32 h (tf32-rounded in-register post-ldmatrix); B = pre-rounded W1.
__global__ void __launch_bounds__(256, 2) gemm_kernel(const float* __restrict__ h,
                                                      const int* __restrict__ tl,
                                                      const float* __restrict__ b1) {
    const int nt = blockIdx.x, tt = blockIdx.y, b = blockIdx.z;
    const int len = tl[b];
    if (tt * BM >= len) return;

    extern __shared__ char smem[];
    float* sb1  = (float*)(smem + SM_B1);
    float* part = (float*)(smem + SM_PART);
    const uint32_t sbase = smem_u32(smem);
    const uint32_t smA = sbase + SM_BUFA;
    const uint32_t smB = sbase + SM_BUFB;

    const int tid = threadIdx.x, lane = tid & 31, wid = tid >> 5;
    const int wm = wid >> 1, wn = wid & 1;

    if (tid < 128) sb1[tid] = b1[nt * BN + tid];

    const float* gA = h      + ((size_t)b * T_SZ + (size_t)tt * BM) * DIN;
    const float* gB = g_w132 + (size_t)nt * BN * DIN;

    float acc[2][8][4];
#pragma unroll
    for (int i = 0; i < 2; i++)
#pragma unroll
        for (int j = 0; j < 8; j++)
#pragma unroll
            for (int k = 0; k < 4; k++) acc[i][j][k] = 0.f;

    // ldmatrix-as-tf32 addressing: each 8x8 b16 matrix = 8 rows x 4 fp32
    const int r8   = lane & 7;
    const uint32_t xorv = (uint32_t)r8 << 4;
    const uint32_t aColSel = ((lane >> 4) & 1) * 16;   // A: mats 2,3 -> cols +4 fp32
    const uint32_t bColSel = ((lane >> 3) & 1) * 16;   // B: mats 1,3 -> k +4
    uint32_t aRowOff[2], bRowOff[4];
#pragma unroll
    for (int mt = 0; mt < 2; mt++)
        aRowOff[mt] = (uint32_t)((wm * 32 + mt * 16 + ((lane >> 3) & 1) * 8 + r8) * 128);
#pragma unroll
    for (int p = 0; p < 4; p++)
        bRowOff[p] = (uint32_t)((wn * 64 + p * 16 + ((lane >> 4) & 1) * 8 + r8) * 128);

    // 3-stage cp.async pipeline
    load_chunk(smA, smB, gA, gB, 0, tid);
    CP_COMMIT();
    load_chunk(smA + 16384, smB + 16384, gA, gB, BK, tid);
    CP_COMMIT();

    for (int c = 0; c < NCHUNK; c++) {
        if (c + 2 < NCHUNK)
            load_chunk(smA + ((c + 2) % 3) * 16384, smB + ((c + 2) % 3) * 16384,
                       gA, gB, (c + 2) * BK, tid);
        CP_COMMIT();          // uniform group count (possibly empty)
        CP_WAIT2();
        __syncthreads();

        const uint32_t bufA = smA + (c % 3) * 16384;
        const uint32_t bufB = smB + (c % 3) * 16384;
#pragma unroll
        for (int ks = 0; ks < 4; ks++) {
            const uint32_t kb = (uint32_t)ks * 32;
            uint32_t a[2][4];
#pragma unroll
            for (int mt = 0; mt < 2; mt++) {
                ldsm_x4(a[mt][0], a[mt][1], a[mt][2], a[mt][3],
                        bufA + aRowOff[mt] + ((kb + aColSel) ^ xorv));
                a[mt][0] = f2tf32u(a[mt][0]); a[mt][1] = f2tf32u(a[mt][1]);
                a[mt][2] = f2tf32u(a[mt][2]); a[mt][3] = f2tf32u(a[mt][3]);
            }
#pragma unroll
            for (int p = 0; p < 4; p++) {
                uint32_t q0, q1, q2, q3;
                ldsm_x4(q0, q1, q2, q3, bufB + bRowOff[p] + ((kb + bColSel) ^ xorv));
                uint32_t bfa[2] = { q0, q1 };
                uint32_t bfb[2] = { q2, q3 };
#pragma unroll
                for (int mt = 0; mt < 2; mt++) {
                    mma_tf32(acc[mt][2 * p],     a[mt], bfa);
                    mma_tf32(acc[mt][2 * p + 1], a[mt], bfb);
                }
            }
        }
        __syncthreads();
    }

    // ---- epilogue: bias + relu + row mask + deterministic column reduce ----
    const int r0g = tt * BM + wm * 32 + (lane >> 2);
#pragma unroll
    for (int n8 = 0; n8 < 8; n8++) {
        const int c0 = wn * 64 + n8 * 8 + (lane & 3) * 2;
        const float bias0 = sb1[c0], bias1 = sb1[c0 + 1];
        float s0 = 0.f, s1 = 0.f;
#pragma unroll
        for (int mt = 0; mt < 2; mt++) {
            const int rr = r0g + mt * 16;
            if (rr < len) {
                s0 += fmaxf(acc[mt][n8][0] + bias0, 0.f);
                s1 += fmaxf(acc[mt][n8][1] + bias1, 0.f);
            }
            if (rr + 8 < len) {
                s0 += fmaxf(acc[mt][n8][2] + bias0, 0.f);
                s1 += fmaxf(acc[mt][n8][3] + bias1, 0.f);
            }
        }
#pragma unroll
        for (int o = 4; o < 32; o <<= 1) {
            s0 += __shfl_xor_sync(0xffffffffu, s0, o);
            s1 += __shfl_xor_sync(0xffffffffu, s1, o);
        }
        if (lane < 4) {
            part[wm * 128 + c0] = s0;
            part[wm * 128 + c0 + 1] = s1;
        }
    }
    __syncthreads();
    if (tid < 128) {
        float v = part[tid] + part[128 + tid] + part[256 + tid] + part[384 + tid];
        g_part[((size_t)tt * B_SZ + b) * HID + nt * BN + tid] = v;
    }
}

// ---------------- reduce partials over t-tiles, divide by len ----------------
__global__ void __launch_bounds__(256) pool_reduce_kernel(const int* __restrict__ tl) {
    int idx = blockIdx.x * 256 + threadIdx.x;   // 65536 = B*HID
    int b = idx >> 11;
    int len = tl[b];
    int ntt = (len + BM - 1) >> 7;
    float s = 0.f;
    for (int t = 0; t < ntt; t++) s += g_part[((size_t)t * B_SZ + b) * HID + (idx & (HID - 1))];
    g_pooled[idx] = s / (float)len;
}

// ---------------- final score ----------------
__global__ void __launch_bounds__(64) score_kernel(const float* __restrict__ W2,
                                                   const float* __restrict__ b2,
                                                   float* __restrict__ out) {
    __shared__ float sm[2][2];
    int b = blockIdx.x, tid = threadIdx.x, wid = tid >> 5, lane = tid & 31;
    float s0 = 0.f, s1 = 0.f;
    const float* p = g_pooled + b * HID;
    for (int h = tid; h < HID; h += 64) {
        float v = p[h];
        s0 += v * W2[h];
        s1 += v * W2[HID + h];
    }
#pragma unroll
    for (int o = 16; o > 0; o >>= 1) {
        s0 += __shfl_xor_sync(0xffffffffu, s0, o);
        s1 += __shfl_xor_sync(0xffffffffu, s1, o);
    }
    if (lane == 0) { sm[wid][0] = s0; sm[wid][1] = s1; }
    __syncthreads();
    if (tid == 0) {
        out[b * 2 + 0] = sm[0][0] + sm[1][0] + b2[0];
        out[b * 2 + 1] = sm[0][1] + sm[1][1] + b2[1];
    }
}

// ---------------- launch ----------------
extern "C" void kernel_launch(void* const* d_in, const int* in_sizes, int n_in,
                              void* d_out, int out_size) {
    const float* h  = (const float*)d_in[0];
    const int*   tl = (const int*)d_in[1];
    const float* W1 = (const float*)d_in[2];
    const float* b1 = (const float*)d_in[3];
    const float* W2 = (const float*)d_in[4];
    const float* b2 = (const float*)d_in[5];
    float* out = (float*)d_out;

    static bool attr_set = false;
    if (!attr_set) {
        cudaFuncSetAttribute(gemm_kernel,
                             cudaFuncAttributeMaxDynamicSharedMemorySize, SMEM_TOTAL);
        attr_set = true;
    }

    rnd_w1_kernel<<<(HID * DIN / 4) / 256, 256>>>((const float4*)W1);
    gemm_kernel<<<dim3(HID / BN, T_SZ / BM, B_SZ), 256, SMEM_TOTAL>>>(h, tl, b1);
    pool_reduce_kernel<<<(B_SZ * HID) / 256, 256>>>(tl);
    score_kernel<<<B_SZ, 64>>>(W2, b2, out);
}